// round 16
// baseline (speedup 1.0000x reference)
#include <cuda_runtime.h>
#include <cuda_bf16.h>
#include <cuda_fp16.h>
#include <math.h>
#include <stdint.h>

// Problem constants
#define CB   4
#define CS   1024
#define CDM  1024
#define CH   16
#define CDK  64
#define CBH  (CB*CH)

// ---------------- scratch (device globals: allocation-free) ----------------
__device__ __half g_scores[(size_t)CBH*CS*CS];           // 128 MB fp16 scores
__device__ __half g_ps [(size_t)CBH*CS*CS];              // 128 MB fp16 (P)
__device__ __half g_vts[2*(size_t)CBH*CDK*CS];           // V^T fp16 hi/lo
__device__ __half g_qhs[(size_t)CBH*CS*CDK];             // Q fp16 (hi only)
__device__ __half g_khs[(size_t)CBH*CS*CDK];             // K fp16 (hi only)
__device__ __half g_qs [(size_t)CB*CS*CDM];              // activations fp16 hi
__device__ __half g_ks [(size_t)CB*CS*CDM];
__device__ __half g_vs [(size_t)CB*CS*CDM];
__device__ __half g_ccs[(size_t)CB*CS*CDM];              // concat fp16 hi
__device__ __half g_wqs[(size_t)CDM*CDM];                // weights fp16 hi
__device__ __half g_wks[(size_t)CDM*CDM];
__device__ __half g_wvs[(size_t)CDM*CDM];
__device__ __half g_wos[(size_t)CDM*CDM];

// ============================================================================
// helpers
// ============================================================================
__device__ __forceinline__ uint32_t smem_u32(const void* p) {
    uint32_t a;
    asm("{ .reg .u64 t; cvta.to.shared.u64 t, %1; cvt.u32.u64 %0, t; }"
        : "=r"(a) : "l"(p));
    return a;
}
__device__ __forceinline__ void cp_async16(uint32_t dst, const void* src) {
    asm volatile("cp.async.cg.shared.global [%0], [%1], 16;"
                 :: "r"(dst), "l"(src) : "memory");
}
__device__ __forceinline__ void cp_commit() {
    asm volatile("cp.async.commit_group;" ::: "memory");
}
template<int N>
__device__ __forceinline__ void cp_wait() {
    asm volatile("cp.async.wait_group %0;" :: "n"(N) : "memory");
}
__device__ __forceinline__ void ldm4(uint32_t* r, uint32_t addr) {
    asm volatile("ldmatrix.sync.aligned.m8n8.x4.shared.b16 {%0,%1,%2,%3}, [%4];"
                 : "=r"(r[0]), "=r"(r[1]), "=r"(r[2]), "=r"(r[3]) : "r"(addr));
}
__device__ __forceinline__ void mma_f16(float* c, const uint32_t* a, const uint32_t* b) {
    asm volatile(
        "mma.sync.aligned.m16n8k16.row.col.f32.f16.f16.f32 "
        "{%0,%1,%2,%3}, {%4,%5,%6,%7}, {%8,%9}, {%0,%1,%2,%3};"
        : "+f"(c[0]), "+f"(c[1]), "+f"(c[2]), "+f"(c[3])
        : "r"(a[0]), "r"(a[1]), "r"(a[2]), "r"(a[3]), "r"(b[0]), "r"(b[1]));
}

// ============================================================================
// Merged fp32 -> fp16 conversion: all 7 tensors in one launch.
// ============================================================================
struct CvtPack {
    const float* src[7];
    __half*      dst[7];
};

__global__ void __launch_bounds__(256) cvt_all_kernel(CvtPack p)
{
    const long i4 = (long)blockIdx.x * 256 + threadIdx.x;   // 0 .. 2^22-1
    int t; long off4;
    if (i4 < 3145728L) {                    // q,k,v
        t = (int)(i4 >> 20);
        off4 = i4 & ((1L << 20) - 1);
    } else {                                // weights
        int u = (int)((i4 - 3145728L) >> 18);
        t = 3 + u;
        off4 = (i4 - 3145728L) & ((1L << 18) - 1);
    }
    const long i = off4 * 4;
    float4 v = *(const float4*)(p.src[t] + i);
    __half h[4];
    h[0] = __float2half(v.x); h[1] = __float2half(v.y);
    h[2] = __float2half(v.z); h[3] = __float2half(v.w);
    *(uint2*)(p.dst[t] + i) = *(uint2*)h;
}

// ============================================================================
// HMMA GEMM (fp16 single-plane operands, fp32 accumulate), BK=32 (R14 proven)
// OUT_MODE 0: fp32 row-major [M,N]
// OUT_MODE 3: fp16 hi/lo planes, transposed head-scatter
// OUT_MODE 4: fp16 single plane, head-scatter
// ============================================================================
#define ROWB 80
#define PLANE 10240
#define BUF   (2*PLANE)          // A, B = 20480
#define MM_SMEM (2*BUF)          // 40960

template<int OUT_MODE>
__global__ void __launch_bounds__(256, 2) mma_gemm_kernel(
    const __half* __restrict__ A,
    const __half* __restrict__ B,
    const float* __restrict__ bias, float* __restrict__ C,
    void* __restrict__ Cpl, long PL,
    int M, int N, int K, float alpha)
{
    extern __shared__ char smem[];
    const uint32_t sbase = smem_u32(smem);

    const int m0 = blockIdx.y * 128;
    const int n0 = blockIdx.x * 128;

    const int tid  = threadIdx.x;
    const int warp = tid >> 5;
    const int lane = tid & 31;
    const int wm   = warp & 3;
    const int wn   = warp >> 2;
    const int lane8 = lane & 7;
    const int lg    = lane >> 3;

    const __half* bases[2];
    bases[0] = A + (size_t)m0 * K;
    bases[1] = B + (size_t)n0 * K;

    float acc[2][8][4];
    #pragma unroll
    for (int i = 0; i < 2; i++)
        #pragma unroll
        for (int j = 0; j < 8; j++)
            #pragma unroll
            for (int c = 0; c < 4; c++) acc[i][j][c] = 0.f;

    const int nch = K >> 5;

    auto load_chunk = [&](int ic, int b) {
        const int k0 = ic * 32;
        #pragma unroll
        for (int i = 0; i < 4; i++) {
            int seg = i * 256 + tid;
            int p   = seg >> 9;
            int r   = (seg >> 2) & 127;
            int c   = seg & 3;
            const __half* src = bases[p] + (size_t)r * K + k0 + c * 8;
            uint32_t dst = sbase + b * BUF + p * PLANE + r * ROWB + c * 16;
            cp_async16(dst, src);
        }
        cp_commit();
    };

    load_chunk(0, 0);
    if (nch > 1) load_chunk(1, 1);

    for (int ic = 0; ic < nch; ic++) {
        const int b = ic & 1;
        if (ic == nch - 1) cp_wait<0>(); else cp_wait<1>();
        __syncthreads();

        const uint32_t bb = sbase + b * BUF;
        #pragma unroll
        for (int kk = 0; kk < 2; kk++) {
            uint32_t ah[2][4];
            #pragma unroll
            for (int tm = 0; tm < 2; tm++) {
                int row = wm * 32 + tm * 16 + lane8 + (lg & 1) * 8;
                int col = kk * 32 + (lg >> 1) * 16;
                ldm4(ah[tm], bb + row * ROWB + col);
            }
            #pragma unroll
            for (int tp = 0; tp < 4; tp++) {
                uint32_t bhf[4];
                int row = wn * 64 + tp * 16 + lane8 + (lg >> 1) * 8;
                int col = kk * 32 + (lg & 1) * 16;
                ldm4(bhf, bb + PLANE + row * ROWB + col);
                #pragma unroll
                for (int tm = 0; tm < 2; tm++) {
                    #pragma unroll
                    for (int h2 = 0; h2 < 2; h2++)
                        mma_f16(acc[tm][tp * 2 + h2], ah[tm], bhf + h2 * 2);
                }
            }
        }
        __syncthreads();
        if (ic + 2 < nch) load_chunk(ic + 2, b);
    }

    // ---- epilogue ----
    const int gid = lane >> 2;
    const int tig = lane & 3;
    #pragma unroll
    for (int tm = 0; tm < 2; tm++) {
        #pragma unroll
        for (int tn = 0; tn < 8; tn++) {
            float* c = acc[tm][tn];
            const int m = m0 + wm * 32 + tm * 16 + gid;
            const int n = n0 + wn * 64 + tn * 8 + tig * 2;
            float b0 = 0.f, b1 = 0.f;
            if (bias) { b0 = bias[n]; b1 = bias[n + 1]; }
            float v00 = c[0] * alpha + b0, v01 = c[1] * alpha + b1;
            float v10 = c[2] * alpha + b0, v11 = c[3] * alpha + b1;
            if (OUT_MODE == 0) {
                *(float2*)(C + (size_t)m * N + n)       = make_float2(v00, v01);
                *(float2*)(C + (size_t)(m + 8) * N + n) = make_float2(v10, v11);
            } else if (OUT_MODE == 3) { // fp16 transposed planes
                __half* P = (__half*)Cpl;
                const int h  = n >> 6;
                const int dk = n & 63;
                #pragma unroll
                for (int rr = 0; rr < 2; rr++) {
                    const int mm = m + rr * 8;
                    const float va = rr ? v10 : v00, vb = rr ? v11 : v01;
                    const int b_ = mm >> 10, s = mm & 1023;
                    size_t base = (((size_t)(b_ * CH + h)) * CDK + dk) * CS + s;
                    __half ha = __float2half(va);
                    __half la = __float2half(va - __half2float(ha));
                    __half hb = __float2half(vb);
                    __half lb = __float2half(vb - __half2float(hb));
                    P[base]           = ha;
                    P[base + PL]      = la;
                    P[base + CS]      = hb;
                    P[base + CS + PL] = lb;
                }
            } else { // OUT_MODE 4: fp16 single plane, head-scatter row-major
                __half* P = (__half*)Cpl;
                const int h  = n >> 6;
                const int dk = n & 63;
                #pragma unroll
                for (int rr = 0; rr < 2; rr++) {
                    const int mm = m + rr * 8;
                    const float va = rr ? v10 : v00, vb = rr ? v11 : v01;
                    const int b_ = mm >> 10, s = mm & 1023;
                    size_t idx = (((size_t)(b_ * CH + h)) * CS + s) * CDK + dk;
                    __half2 hp = __floats2half2_rn(va, vb);
                    *(uint32_t*)(P + idx) = *(uint32_t*)&hp;
                }
            }
        }
    }
}

// ============================================================================
// QK^T scores kernel (fp16 Q hi x K hi, K=64 single shot) -> fp16 scores
// ============================================================================
#define QKROWB 144
#define QKPLANE (128*QKROWB)
#define QK_SMEM (2*QKPLANE)

__global__ void __launch_bounds__(256, 2) qk_gemm_kernel(
    const __half* __restrict__ Qg,
    const __half* __restrict__ Kg,
    __half* __restrict__ S)
{
    extern __shared__ char smem[];
    const uint32_t sbase = smem_u32(smem);

    const int z  = blockIdx.z;
    const int m0 = blockIdx.y * 128;
    const int n0 = blockIdx.x * 128;
    const __half* Qz = Qg + ((size_t)z * CS + m0) * CDK;
    const __half* Kz = Kg + ((size_t)z * CS + n0) * CDK;
    __half* Sz = S + (size_t)z * CS * CS;

    const int tid  = threadIdx.x;
    const int warp = tid >> 5;
    const int lane = tid & 31;
    const int wm   = warp & 3;
    const int wn   = warp >> 2;
    const int lane8 = lane & 7;
    const int lg    = lane >> 3;

    #pragma unroll
    for (int i = 0; i < 8; i++) {
        int seg = i * 256 + tid;
        int p   = seg >> 10;
        int r   = (seg >> 3) & 127;
        int c   = seg & 7;
        const __half* src = (p == 0) ? Qz + (size_t)r * CDK + c * 8
                                     : Kz + (size_t)r * CDK + c * 8;
        cp_async16(sbase + p * QKPLANE + r * QKROWB + c * 16, src);
    }
    cp_commit();
    cp_wait<0>();
    __syncthreads();

    float acc[2][8][4];
    #pragma unroll
    for (int i = 0; i < 2; i++)
        #pragma unroll
        for (int j = 0; j < 8; j++)
            #pragma unroll
            for (int c = 0; c < 4; c++) acc[i][j][c] = 0.f;

    #pragma unroll
    for (int ks = 0; ks < 4; ks++) {
        uint32_t qf[2][4];
        #pragma unroll
        for (int tm = 0; tm < 2; tm++) {
            int row = wm * 32 + tm * 16 + lane8 + (lg & 1) * 8;
            int col = ks * 32 + (lg >> 1) * 16;
            ldm4(qf[tm], sbase + row * QKROWB + col);
        }
        #pragma unroll
        for (int tp = 0; tp < 4; tp++) {
            uint32_t kh[4];
            int row = wn * 64 + tp * 16 + lane8 + (lg >> 1) * 8;
            int col = ks * 32 + (lg & 1) * 16;
            ldm4(kh, sbase + QKPLANE + row * QKROWB + col);
            #pragma unroll
            for (int tm = 0; tm < 2; tm++) {
                #pragma unroll
                for (int h2 = 0; h2 < 2; h2++)
                    mma_f16(acc[tm][tp * 2 + h2], qf[tm], kh + h2 * 2);
            }
        }
    }

    const int gid = lane >> 2;
    const int tig = lane & 3;
    #pragma unroll
    for (int tm = 0; tm < 2; tm++) {
        #pragma unroll
        for (int tn = 0; tn < 8; tn++) {
            float* c = acc[tm][tn];
            const int m = m0 + wm * 32 + tm * 16 + gid;
            const int n = n0 + wn * 64 + tn * 8 + tig * 2;
            __half2 lo = __floats2half2_rn(c[0] * 0.125f, c[1] * 0.125f);
            __half2 hi = __floats2half2_rn(c[2] * 0.125f, c[3] * 0.125f);
            *(uint32_t*)(Sz + (size_t)m * CS + n)       = *(uint32_t*)&lo;
            *(uint32_t*)(Sz + (size_t)(m + 8) * CS + n) = *(uint32_t*)&hi;
        }
    }
}

// ============================================================================
// Row-ops: warp per row, no barriers, no smem. Reads fp16 scores.
// ============================================================================
__global__ void __launch_bounds__(256) rowops_kernel(
    const __half* __restrict__ scores, const float* __restrict__ gammas,
    __half* __restrict__ Pout)
{
    const long gid = (long)blockIdx.x * 8 + (threadIdx.x >> 5);
    const int lane = threadIdx.x & 31;
    const int i = (int)(gid & (CS - 1));
    const int h = (int)((gid >> 10) & (CH - 1));
    const __half* row = scores + gid * CS;

    float s[32];
    #pragma unroll
    for (int g = 0; g < 8; g++) {
        uint2 pk = *(const uint2*)(row + g * 128 + lane * 4);
        float2 f0 = __half22float2(*(__half2*)&pk.x);
        float2 f1 = __half22float2(*(__half2*)&pk.y);
        s[g*4+0] = f0.x; s[g*4+1] = f0.y;
        s[g*4+2] = f1.x; s[g*4+3] = f1.y;
    }

    float mx = s[0];
    #pragma unroll
    for (int q = 1; q < 32; q++) mx = fmaxf(mx, s[q]);
    #pragma unroll
    for (int o = 16; o; o >>= 1) mx = fmaxf(mx, __shfl_xor_sync(0xffffffffu, mx, o));

    float e[32];
    float zl = 0.f;
    #pragma unroll
    for (int q = 0; q < 32; q++) { e[q] = __expf(s[q] - mx); zl += e[q]; }
    #pragma unroll
    for (int o = 16; o; o >>= 1) zl += __shfl_xor_sync(0xffffffffu, zl, o);
    const float invZ = 1.f / zl;

    const int glim = i >> 7;

    float carry = 0.f;
    #pragma unroll
    for (int g = 0; g < 8; g++) {
        if (g <= glim) {
            const int j0 = g * 128 + lane * 4;
            float m0 = (j0 + 0 <= i) ? e[g*4+0] : 0.f;
            float m1 = (j0 + 1 <= i) ? e[g*4+1] : 0.f;
            float m2 = (j0 + 2 <= i) ? e[g*4+2] : 0.f;
            float m3 = (j0 + 3 <= i) ? e[g*4+3] : 0.f;
            float l0 = m0, l1 = l0 + m1, l2 = l1 + m2, l3 = l2 + m3;
            float x = l3;
            #pragma unroll
            for (int d = 1; d < 32; d <<= 1) {
                float y = __shfl_up_sync(0xffffffffu, x, d);
                if (lane >= d) x += y;
            }
            float excl = x - l3;
            float tot  = __shfl_sync(0xffffffffu, x, 31);
            e[g*4+0] = carry + excl + l0;
            e[g*4+1] = carry + excl + l1;
            e[g*4+2] = carry + excl + l2;
            e[g*4+3] = carry + excl + l3;
            carry += tot;
        }
    }
    const float T = carry;

    const float g_  = gammas[h];
    const float gamma = -((g_ > 20.f) ? g_ : log1pf(__expf(g_)));
    const float NEG_INF = -__int_as_float(0x7f800000);
    #pragma unroll
    for (int g = 0; g < 8; g++) {
        if (g <= glim) {
            const int j0 = g * 128 + lane * 4;
            #pragma unroll
            for (int q = 0; q < 4; q++) {
                const int j = j0 + q;
                if (j <= i) {
                    float d2 = fmaxf((T - e[g*4+q]) * invZ * (float)(i - j), 0.f);
                    float eff = fminf(fmaxf(__expf(gamma * sqrtf(d2)), 1e-5f), 1e5f);
                    s[g*4+q] = s[g*4+q] * eff;
                } else {
                    s[g*4+q] = NEG_INF;
                }
            }
        }
    }

    float mx2 = NEG_INF;
    #pragma unroll
    for (int g = 0; g < 8; g++)
        if (g <= glim) {
            #pragma unroll
            for (int q = 0; q < 4; q++) mx2 = fmaxf(mx2, s[g*4+q]);
        }
    #pragma unroll
    for (int o = 16; o; o >>= 1) mx2 = fmaxf(mx2, __shfl_xor_sync(0xffffffffu, mx2, o));

    float z2 = 0.f;
    #pragma unroll
    for (int g = 0; g < 8; g++)
        if (g <= glim) {
            #pragma unroll
            for (int q = 0; q < 4; q++) {
                s[g*4+q] = __expf(s[g*4+q] - mx2);
                z2 += s[g*4+q];
            }
        }
    #pragma unroll
    for (int o = 16; o; o >>= 1) z2 += __shfl_xor_sync(0xffffffffu, z2, o);
    const float invZ2 = 1.f / z2;

    __half* prow = Pout + gid * CS;
    #pragma unroll
    for (int g = 0; g < 8; g++) {
        if (g <= glim) {
            __half2 p0 = __floats2half2_rn(s[g*4+0] * invZ2, s[g*4+1] * invZ2);
            __half2 p1 = __floats2half2_rn(s[g*4+2] * invZ2, s[g*4+3] * invZ2);
            uint2 pk;
            pk.x = *(uint32_t*)&p0;
            pk.y = *(uint32_t*)&p1;
            *(uint2*)(prow + g * 128 + lane * 4) = pk;
        }
    }
}

// ============================================================================
// AV HMMA (triangular, heavy-blocks-first) -> concat fp16 single plane
// ============================================================================
#define AROWB 144
#define AP_BYTES (128*AROWB)
#define AV_BYTES (2*64*AROWB)
#define AV_BUF (AP_BYTES + AV_BYTES)
#define AV_SMEM (2*AV_BUF)

__global__ void __launch_bounds__(256, 2) av_mma_kernel(
    const __half* __restrict__ Pg, const __half* __restrict__ Vt, long PLV,
    __half* __restrict__ Cc)
{
    extern __shared__ char smem[];
    const uint32_t sbase = smem_u32(smem);

    const int z  = blockIdx.z;
    const int yb = gridDim.y - 1 - blockIdx.y;
    const int m0 = yb * 128;
    const __half* Pz = Pg + (size_t)z * CS * CS;
    const __half* Vz = Vt + (size_t)z * CDK * CS;

    const int tid  = threadIdx.x;
    const int warp = tid >> 5;
    const int lane = tid & 31;
    const int wm   = warp & 3;
    const int wn   = warp >> 2;
    const int lane8 = lane & 7;
    const int lg    = lane >> 3;

    float acc[2][4][4];
    #pragma unroll
    for (int i = 0; i < 2; i++)
        #pragma unroll
        for (int j = 0; j < 4; j++)
            #pragma unroll
            for (int c = 0; c < 4; c++) acc[i][j][c] = 0.f;

    const int nch = 2 * (yb + 1);

    auto load_chunk = [&](int ic, int b) {
        const int k0 = ic * 64;
        #pragma unroll
        for (int i = 0; i < 8; i++) {
            int seg = i * 256 + tid;
            int part = seg >> 10;
            int r    = (seg >> 3) & 127;
            int c    = seg & 7;
            uint32_t dstb = sbase + b * AV_BUF;
            if (part == 0) {
                const __half* src = Pz + (size_t)(m0 + r) * CS + k0 + c * 8;
                cp_async16(dstb + r * AROWB + c * 16, src);
            } else {
                int pl = r >> 6, rr2 = r & 63;
                const __half* src = Vz + (size_t)pl * PLV + (size_t)rr2 * CS + k0 + c * 8;
                cp_async16(dstb + AP_BYTES + pl * (64 * AROWB) + rr2 * AROWB + c * 16, src);
            }
        }
        cp_commit();
    };

    load_chunk(0, 0);
    load_chunk(1, 1);

    for (int ic = 0; ic < nch; ic++) {
        const int b = ic & 1;
        if (ic == nch - 1) cp_wait<0>(); else cp_wait<1>();
        __syncthreads();

        const uint32_t bb = sbase + b * AV_BUF;
        #pragma unroll
        for (int kk = 0; kk < 4; kk++) {
            uint32_t af[2][4];
            #pragma unroll
            for (int tm = 0; tm < 2; tm++) {
                int row = wm * 32 + tm * 16 + lane8 + (lg & 1) * 8;
                int col = kk * 32 + (lg >> 1) * 16;
                ldm4(af[tm], bb + row * AROWB + col);
            }
            #pragma unroll
            for (int tp = 0; tp < 2; tp++) {
                uint32_t bhf[4], blf[4];
                int row = wn * 32 + tp * 16 + lane8 + (lg >> 1) * 8;
                int col = kk * 32 + (lg & 1) * 16;
                uint32_t addr = bb + AP_BYTES + row * AROWB + col;
                ldm4(bhf, addr);
                ldm4(blf, addr + 64 * AROWB);
                #pragma unroll
                for (int tm = 0; tm < 2; tm++) {
                    #pragma unroll
                    for (int h2 = 0; h2 < 2; h2++) {
                        float* c = acc[tm][tp * 2 + h2];
                        mma_f16(c, af[tm], bhf + h2 * 2);
                        mma_f16(c, af[tm], blf + h2 * 2);
                    }
                }
            }
        }
        __syncthreads();
        if (ic + 2 < nch) load_chunk(ic + 2, b);
    }

    const int gid = lane >> 2;
    const int tig = lane & 3;
    const int b_ = z >> 4;
    const int h  = z & 15;
    #pragma unroll
    for (int tm = 0; tm < 2; tm++) {
        #pragma unroll
        for (int tn = 0; tn < 4; tn++) {
            float* c = acc[tm][tn];
            const int m = m0 + wm * 32 + tm * 16 + gid;
            const int n = wn * 32 + tn * 8 + tig * 2;
            #pragma unroll
            for (int rr = 0; rr < 2; rr++) {
                const int s = m + rr * 8;
                const float va = c[rr * 2 + 0], vb = c[rr * 2 + 1];
                size_t idx = ((size_t)(b_ * CS + s)) * CDM + h * CDK + n;
                __half2 hp = __floats2half2_rn(va, vb);
                *(uint32_t*)(Cc + idx) = *(uint32_t*)&hp;
            }
        }
    }
}

// ============================================================================
// Launch sequence
// ============================================================================
extern "C" void kernel_launch(void* const* d_in, const int* in_sizes, int n_in,
                              void* d_out, int out_size)
{
    const float* q      = (const float*)d_in[0];
    const float* k      = (const float*)d_in[1];
    const float* v      = (const float*)d_in[2];
    const float* Wq     = (const float*)d_in[3];
    const float* bq     = (const float*)d_in[4];
    const float* Wk     = (const float*)d_in[5];
    const float* bk     = (const float*)d_in[6];
    const float* Wv     = (const float*)d_in[7];
    const float* bv     = (const float*)d_in[8];
    const float* Wo     = (const float*)d_in[9];
    const float* bo     = (const float*)d_in[10];
    const float* gammas = (const float*)d_in[11];
    float* out = (float*)d_out;

    __half *sc, *ps, *vts, *qhs, *khs, *qs, *ks, *vs, *ccs, *wqs, *wks, *wvs, *wos;
    cudaGetSymbolAddress((void**)&sc,  g_scores);
    cudaGetSymbolAddress((void**)&ps,  g_ps);
    cudaGetSymbolAddress((void**)&vts, g_vts);
    cudaGetSymbolAddress((void**)&qhs, g_qhs);
    cudaGetSymbolAddress((void**)&khs, g_khs);
    cudaGetSymbolAddress((void**)&qs,  g_qs);
    cudaGetSymbolAddress((void**)&ks,  g_ks);
    cudaGetSymbolAddress((void**)&vs,  g_vs);
    cudaGetSymbolAddress((void**)&ccs, g_ccs);
    cudaGetSymbolAddress((void**)&wqs, g_wqs);
    cudaGetSymbolAddress((void**)&wks, g_wks);
    cudaGetSymbolAddress((void**)&wvs, g_wvs);
    cudaGetSymbolAddress((void**)&wos, g_wos);

    cudaFuncSetAttribute((const void*)mma_gemm_kernel<4>, cudaFuncAttributeMaxDynamicSharedMemorySize, MM_SMEM);
    cudaFuncSetAttribute((const void*)mma_gemm_kernel<3>, cudaFuncAttributeMaxDynamicSharedMemorySize, MM_SMEM);
    cudaFuncSetAttribute((const void*)mma_gemm_kernel<0>, cudaFuncAttributeMaxDynamicSharedMemorySize, MM_SMEM);
    cudaFuncSetAttribute(qk_gemm_kernel, cudaFuncAttributeMaxDynamicSharedMemorySize, QK_SMEM);
    cudaFuncSetAttribute(av_mma_kernel,  cudaFuncAttributeMaxDynamicSharedMemorySize, AV_SMEM);

    const int  M    = CB * CS;              // 4096
    const long nH   = (long)CBH * CS * CDK; // 4 M elems

    // all fp32 -> fp16 conversions in one launch
    CvtPack cp;
    cp.src[0] = q;  cp.dst[0] = qs;
    cp.src[1] = k;  cp.dst[1] = ks;
    cp.src[2] = v;  cp.dst[2] = vs;
    cp.src[3] = Wq; cp.dst[3] = wqs;
    cp.src[4] = Wk; cp.dst[4] = wks;
    cp.src[5] = Wv; cp.dst[5] = wvs;
    cp.src[6] = Wo; cp.dst[6] = wos;
    cvt_all_kernel<<<16384, 256>>>(cp);

    // Q/K -> fp16 single plane (head-scattered)
    mma_gemm_kernel<4><<<dim3(CDM/128, M/128), 256, MM_SMEM>>>(
        qs, wqs, bq, nullptr, qhs, 0, M, CDM, CDM, 1.f);
    mma_gemm_kernel<4><<<dim3(CDM/128, M/128), 256, MM_SMEM>>>(
        ks, wks, bk, nullptr, khs, 0, M, CDM, CDM, 1.f);
    // V -> fp16 split planes transposed
    mma_gemm_kernel<3><<<dim3(CDM/128, M/128), 256, MM_SMEM>>>(
        vs, wvs, bv, nullptr, vts, nH, M, CDM, CDM, 1.f);

    // scores = Qh @ Kh^T / 8 (fp16 out), batched over bh
    qk_gemm_kernel<<<dim3(CS/128, CS/128, CBH), 256, QK_SMEM>>>(qhs, khs, sc);

    // row ops (warp per row) -> fp16 P (causal-limited writes)
    rowops_kernel<<<CBH * CS / 8, 256>>>(sc, gammas, ps);

    // AV (triangular, heavy-first) -> concat fp16 single plane
    av_mma_kernel<<<dim3(1, CS/128, CBH), 256, AV_SMEM>>>(ps, vts, nH, ccs);

    // output projection
    mma_gemm_kernel<0><<<dim3(CDM/128, M/128), 256, MM_SMEM>>>(
        ccs, wos, bo, out, nullptr, 0, M, CDM, CDM, 1.f);
}

// round 17
// speedup vs baseline: 1.1253x; 1.1253x over previous
#include <cuda_runtime.h>
#include <cuda_bf16.h>
#include <cuda_fp16.h>
#include <math.h>
#include <stdint.h>

// Problem constants
#define CB   4
#define CS   1024
#define CDM  1024
#define CH   16
#define CDK  64
#define CBH  (CB*CH)

// ---------------- scratch (device globals: allocation-free) ----------------
__device__ __half g_scores[(size_t)CBH*CS*CS];           // 128 MB fp16 scores
__device__ __half g_ps [(size_t)CBH*CS*CS];              // 128 MB fp16 (P)
__device__ __half g_vts[(size_t)CBH*CDK*CS];             // V^T fp16 (hi only)
__device__ __half g_qhs[(size_t)CBH*CS*CDK];             // Q fp16 (hi only)
__device__ __half g_khs[(size_t)CBH*CS*CDK];             // K fp16 (hi only)
__device__ __half g_qs [(size_t)CB*CS*CDM];              // activations fp16 hi
__device__ __half g_ks [(size_t)CB*CS*CDM];
__device__ __half g_vs [(size_t)CB*CS*CDM];
__device__ __half g_ccs[(size_t)CB*CS*CDM];              // concat fp16 hi
__device__ __half g_wqs[(size_t)CDM*CDM];                // weights fp16 hi
__device__ __half g_wks[(size_t)CDM*CDM];
__device__ __half g_wvs[(size_t)CDM*CDM];
__device__ __half g_wos[(size_t)CDM*CDM];

// ============================================================================
// helpers
// ============================================================================
__device__ __forceinline__ uint32_t smem_u32(const void* p) {
    uint32_t a;
    asm("{ .reg .u64 t; cvta.to.shared.u64 t, %1; cvt.u32.u64 %0, t; }"
        : "=r"(a) : "l"(p));
    return a;
}
__device__ __forceinline__ void cp_async16(uint32_t dst, const void* src) {
    asm volatile("cp.async.cg.shared.global [%0], [%1], 16;"
                 :: "r"(dst), "l"(src) : "memory");
}
__device__ __forceinline__ void cp_commit() {
    asm volatile("cp.async.commit_group;" ::: "memory");
}
template<int N>
__device__ __forceinline__ void cp_wait() {
    asm volatile("cp.async.wait_group %0;" :: "n"(N) : "memory");
}
__device__ __forceinline__ void ldm4(uint32_t* r, uint32_t addr) {
    asm volatile("ldmatrix.sync.aligned.m8n8.x4.shared.b16 {%0,%1,%2,%3}, [%4];"
                 : "=r"(r[0]), "=r"(r[1]), "=r"(r[2]), "=r"(r[3]) : "r"(addr));
}
__device__ __forceinline__ void mma_f16(float* c, const uint32_t* a, const uint32_t* b) {
    asm volatile(
        "mma.sync.aligned.m16n8k16.row.col.f32.f16.f16.f32 "
        "{%0,%1,%2,%3}, {%4,%5,%6,%7}, {%8,%9}, {%0,%1,%2,%3};"
        : "+f"(c[0]), "+f"(c[1]), "+f"(c[2]), "+f"(c[3])
        : "r"(a[0]), "r"(a[1]), "r"(a[2]), "r"(a[3]), "r"(b[0]), "r"(b[1]));
}

// ============================================================================
// fp32 -> fp16 (hi only)  [R14-proven: one launch per tensor]
// ============================================================================
__global__ void __launch_bounds__(256) cvt_f16_kernel(
    const float* __restrict__ x, __half* __restrict__ out, long n)
{
    long i = ((long)blockIdx.x * blockDim.x + threadIdx.x) * 4;
    if (i >= n) return;
    float4 v = *(const float4*)(x + i);
    __half h[4];
    h[0] = __float2half(v.x); h[1] = __float2half(v.y);
    h[2] = __float2half(v.z); h[3] = __float2half(v.w);
    *(uint2*)(out + i) = *(uint2*)h;
}

// ============================================================================
// HMMA GEMM (fp16 single-plane operands, fp32 accumulate), BK=32 (R14)
// OUT_MODE 0: fp32 row-major [M,N]
// OUT_MODE 3: fp16 single plane, transposed head-scatter
// OUT_MODE 4: fp16 single plane, head-scatter
// ============================================================================
#define ROWB 80
#define PLANE 10240
#define BUF   (2*PLANE)          // A, B = 20480
#define MM_SMEM (2*BUF)          // 40960

template<int OUT_MODE>
__global__ void __launch_bounds__(256, 2) mma_gemm_kernel(
    const __half* __restrict__ A,
    const __half* __restrict__ B,
    const float* __restrict__ bias, float* __restrict__ C,
    void* __restrict__ Cpl,
    int M, int N, int K, float alpha)
{
    extern __shared__ char smem[];
    const uint32_t sbase = smem_u32(smem);

    const int m0 = blockIdx.y * 128;
    const int n0 = blockIdx.x * 128;

    const int tid  = threadIdx.x;
    const int warp = tid >> 5;
    const int lane = tid & 31;
    const int wm   = warp & 3;
    const int wn   = warp >> 2;
    const int lane8 = lane & 7;
    const int lg    = lane >> 3;

    const __half* bases[2];
    bases[0] = A + (size_t)m0 * K;
    bases[1] = B + (size_t)n0 * K;

    float acc[2][8][4];
    #pragma unroll
    for (int i = 0; i < 2; i++)
        #pragma unroll
        for (int j = 0; j < 8; j++)
            #pragma unroll
            for (int c = 0; c < 4; c++) acc[i][j][c] = 0.f;

    const int nch = K >> 5;

    auto load_chunk = [&](int ic, int b) {
        const int k0 = ic * 32;
        #pragma unroll
        for (int i = 0; i < 4; i++) {
            int seg = i * 256 + tid;
            int p   = seg >> 9;
            int r   = (seg >> 2) & 127;
            int c   = seg & 3;
            const __half* src = bases[p] + (size_t)r * K + k0 + c * 8;
            uint32_t dst = sbase + b * BUF + p * PLANE + r * ROWB + c * 16;
            cp_async16(dst, src);
        }
        cp_commit();
    };

    load_chunk(0, 0);
    if (nch > 1) load_chunk(1, 1);

    for (int ic = 0; ic < nch; ic++) {
        const int b = ic & 1;
        if (ic == nch - 1) cp_wait<0>(); else cp_wait<1>();
        __syncthreads();

        const uint32_t bb = sbase + b * BUF;
        #pragma unroll
        for (int kk = 0; kk < 2; kk++) {
            uint32_t ah[2][4];
            #pragma unroll
            for (int tm = 0; tm < 2; tm++) {
                int row = wm * 32 + tm * 16 + lane8 + (lg & 1) * 8;
                int col = kk * 32 + (lg >> 1) * 16;
                ldm4(ah[tm], bb + row * ROWB + col);
            }
            #pragma unroll
            for (int tp = 0; tp < 4; tp++) {
                uint32_t bhf[4];
                int row = wn * 64 + tp * 16 + lane8 + (lg >> 1) * 8;
                int col = kk * 32 + (lg & 1) * 16;
                ldm4(bhf, bb + PLANE + row * ROWB + col);
                #pragma unroll
                for (int tm = 0; tm < 2; tm++) {
                    #pragma unroll
                    for (int h2 = 0; h2 < 2; h2++)
                        mma_f16(acc[tm][tp * 2 + h2], ah[tm], bhf + h2 * 2);
                }
            }
        }
        __syncthreads();
        if (ic + 2 < nch) load_chunk(ic + 2, b);
    }

    // ---- epilogue ----
    const int gid = lane >> 2;
    const int tig = lane & 3;
    #pragma unroll
    for (int tm = 0; tm < 2; tm++) {
        #pragma unroll
        for (int tn = 0; tn < 8; tn++) {
            float* c = acc[tm][tn];
            const int m = m0 + wm * 32 + tm * 16 + gid;
            const int n = n0 + wn * 64 + tn * 8 + tig * 2;
            float b0 = 0.f, b1 = 0.f;
            if (bias) { b0 = bias[n]; b1 = bias[n + 1]; }
            float v00 = c[0] * alpha + b0, v01 = c[1] * alpha + b1;
            float v10 = c[2] * alpha + b0, v11 = c[3] * alpha + b1;
            if (OUT_MODE == 0) {
                *(float2*)(C + (size_t)m * N + n)       = make_float2(v00, v01);
                *(float2*)(C + (size_t)(m + 8) * N + n) = make_float2(v10, v11);
            } else if (OUT_MODE == 3) { // fp16 single plane, transposed
                __half* P = (__half*)Cpl;
                const int h  = n >> 6;
                const int dk = n & 63;
                #pragma unroll
                for (int rr = 0; rr < 2; rr++) {
                    const int mm = m + rr * 8;
                    const float va = rr ? v10 : v00, vb = rr ? v11 : v01;
                    const int b_ = mm >> 10, s = mm & 1023;
                    size_t base = (((size_t)(b_ * CH + h)) * CDK + dk) * CS + s;
                    P[base]      = __float2half(va);
                    P[base + CS] = __float2half(vb);
                }
            } else { // OUT_MODE 4: fp16 single plane, head-scatter row-major
                __half* P = (__half*)Cpl;
                const int h  = n >> 6;
                const int dk = n & 63;
                #pragma unroll
                for (int rr = 0; rr < 2; rr++) {
                    const int mm = m + rr * 8;
                    const float va = rr ? v10 : v00, vb = rr ? v11 : v01;
                    const int b_ = mm >> 10, s = mm & 1023;
                    size_t idx = (((size_t)(b_ * CH + h)) * CS + s) * CDK + dk;
                    __half2 hp = __floats2half2_rn(va, vb);
                    *(uint32_t*)(P + idx) = *(uint32_t*)&hp;
                }
            }
        }
    }
}

// ============================================================================
// QK^T scores kernel (fp16 Q hi x K hi, K=64 single shot) -> fp16 scores
// ============================================================================
#define QKROWB 144
#define QKPLANE (128*QKROWB)
#define QK_SMEM (2*QKPLANE)

__global__ void __launch_bounds__(256, 2) qk_gemm_kernel(
    const __half* __restrict__ Qg,
    const __half* __restrict__ Kg,
    __half* __restrict__ S)
{
    extern __shared__ char smem[];
    const uint32_t sbase = smem_u32(smem);

    const int z  = blockIdx.z;
    const int m0 = blockIdx.y * 128;
    const int n0 = blockIdx.x * 128;
    const __half* Qz = Qg + ((size_t)z * CS + m0) * CDK;
    const __half* Kz = Kg + ((size_t)z * CS + n0) * CDK;
    __half* Sz = S + (size_t)z * CS * CS;

    const int tid  = threadIdx.x;
    const int warp = tid >> 5;
    const int lane = tid & 31;
    const int wm   = warp & 3;
    const int wn   = warp >> 2;
    const int lane8 = lane & 7;
    const int lg    = lane >> 3;

    #pragma unroll
    for (int i = 0; i < 8; i++) {
        int seg = i * 256 + tid;
        int p   = seg >> 10;
        int r   = (seg >> 3) & 127;
        int c   = seg & 7;
        const __half* src = (p == 0) ? Qz + (size_t)r * CDK + c * 8
                                     : Kz + (size_t)r * CDK + c * 8;
        cp_async16(sbase + p * QKPLANE + r * QKROWB + c * 16, src);
    }
    cp_commit();
    cp_wait<0>();
    __syncthreads();

    float acc[2][8][4];
    #pragma unroll
    for (int i = 0; i < 2; i++)
        #pragma unroll
        for (int j = 0; j < 8; j++)
            #pragma unroll
            for (int c = 0; c < 4; c++) acc[i][j][c] = 0.f;

    #pragma unroll
    for (int ks = 0; ks < 4; ks++) {
        uint32_t qf[2][4];
        #pragma unroll
        for (int tm = 0; tm < 2; tm++) {
            int row = wm * 32 + tm * 16 + lane8 + (lg & 1) * 8;
            int col = ks * 32 + (lg >> 1) * 16;
            ldm4(qf[tm], sbase + row * QKROWB + col);
        }
        #pragma unroll
        for (int tp = 0; tp < 4; tp++) {
            uint32_t kh[4];
            int row = wn * 64 + tp * 16 + lane8 + (lg >> 1) * 8;
            int col = ks * 32 + (lg & 1) * 16;
            ldm4(kh, sbase + QKPLANE + row * QKROWB + col);
            #pragma unroll
            for (int tm = 0; tm < 2; tm++) {
                #pragma unroll
                for (int h2 = 0; h2 < 2; h2++)
                    mma_f16(acc[tm][tp * 2 + h2], qf[tm], kh + h2 * 2);
            }
        }
    }

    const int gid = lane >> 2;
    const int tig = lane & 3;
    #pragma unroll
    for (int tm = 0; tm < 2; tm++) {
        #pragma unroll
        for (int tn = 0; tn < 8; tn++) {
            float* c = acc[tm][tn];
            const int m = m0 + wm * 32 + tm * 16 + gid;
            const int n = n0 + wn * 64 + tn * 8 + tig * 2;
            __half2 lo = __floats2half2_rn(c[0] * 0.125f, c[1] * 0.125f);
            __half2 hi = __floats2half2_rn(c[2] * 0.125f, c[3] * 0.125f);
            *(uint32_t*)(Sz + (size_t)m * CS + n)       = *(uint32_t*)&lo;
            *(uint32_t*)(Sz + (size_t)(m + 8) * CS + n) = *(uint32_t*)&hi;
        }
    }
}

// ============================================================================
// Row-ops: warp per row, no barriers, no smem. Reads fp16 scores.
// ============================================================================
__global__ void __launch_bounds__(256) rowops_kernel(
    const __half* __restrict__ scores, const float* __restrict__ gammas,
    __half* __restrict__ Pout)
{
    const long gid = (long)blockIdx.x * 8 + (threadIdx.x >> 5);
    const int lane = threadIdx.x & 31;
    const int i = (int)(gid & (CS - 1));
    const int h = (int)((gid >> 10) & (CH - 1));
    const __half* row = scores + gid * CS;

    float s[32];
    #pragma unroll
    for (int g = 0; g < 8; g++) {
        uint2 pk = *(const uint2*)(row + g * 128 + lane * 4);
        float2 f0 = __half22float2(*(__half2*)&pk.x);
        float2 f1 = __half22float2(*(__half2*)&pk.y);
        s[g*4+0] = f0.x; s[g*4+1] = f0.y;
        s[g*4+2] = f1.x; s[g*4+3] = f1.y;
    }

    float mx = s[0];
    #pragma unroll
    for (int q = 1; q < 32; q++) mx = fmaxf(mx, s[q]);
    #pragma unroll
    for (int o = 16; o; o >>= 1) mx = fmaxf(mx, __shfl_xor_sync(0xffffffffu, mx, o));

    float e[32];
    float zl = 0.f;
    #pragma unroll
    for (int q = 0; q < 32; q++) { e[q] = __expf(s[q] - mx); zl += e[q]; }
    #pragma unroll
    for (int o = 16; o; o >>= 1) zl += __shfl_xor_sync(0xffffffffu, zl, o);
    const float invZ = 1.f / zl;

    const int glim = i >> 7;

    float carry = 0.f;
    #pragma unroll
    for (int g = 0; g < 8; g++) {
        if (g <= glim) {
            const int j0 = g * 128 + lane * 4;
            float m0 = (j0 + 0 <= i) ? e[g*4+0] : 0.f;
            float m1 = (j0 + 1 <= i) ? e[g*4+1] : 0.f;
            float m2 = (j0 + 2 <= i) ? e[g*4+2] : 0.f;
            float m3 = (j0 + 3 <= i) ? e[g*4+3] : 0.f;
            float l0 = m0, l1 = l0 + m1, l2 = l1 + m2, l3 = l2 + m3;
            float x = l3;
            #pragma unroll
            for (int d = 1; d < 32; d <<= 1) {
                float y = __shfl_up_sync(0xffffffffu, x, d);
                if (lane >= d) x += y;
            }
            float excl = x - l3;
            float tot  = __shfl_sync(0xffffffffu, x, 31);
            e[g*4+0] = carry + excl + l0;
            e[g*4+1] = carry + excl + l1;
            e[g*4+2] = carry + excl + l2;
            e[g*4+3] = carry + excl + l3;
            carry += tot;
        }
    }
    const float T = carry;

    const float g_  = gammas[h];
    const float gamma = -((g_ > 20.f) ? g_ : log1pf(__expf(g_)));
    const float NEG_INF = -__int_as_float(0x7f800000);
    #pragma unroll
    for (int g = 0; g < 8; g++) {
        if (g <= glim) {
            const int j0 = g * 128 + lane * 4;
            #pragma unroll
            for (int q = 0; q < 4; q++) {
                const int j = j0 + q;
                if (j <= i) {
                    float d2 = fmaxf((T - e[g*4+q]) * invZ * (float)(i - j), 0.f);
                    float eff = fminf(fmaxf(__expf(gamma * sqrtf(d2)), 1e-5f), 1e5f);
                    s[g*4+q] = s[g*4+q] * eff;
                } else {
                    s[g*4+q] = NEG_INF;
                }
            }
        }
    }

    float mx2 = NEG_INF;
    #pragma unroll
    for (int g = 0; g < 8; g++)
        if (g <= glim) {
            #pragma unroll
            for (int q = 0; q < 4; q++) mx2 = fmaxf(mx2, s[g*4+q]);
        }
    #pragma unroll
    for (int o = 16; o; o >>= 1) mx2 = fmaxf(mx2, __shfl_xor_sync(0xffffffffu, mx2, o));

    float z2 = 0.f;
    #pragma unroll
    for (int g = 0; g < 8; g++)
        if (g <= glim) {
            #pragma unroll
            for (int q = 0; q < 4; q++) {
                s[g*4+q] = __expf(s[g*4+q] - mx2);
                z2 += s[g*4+q];
            }
        }
    #pragma unroll
    for (int o = 16; o; o >>= 1) z2 += __shfl_xor_sync(0xffffffffu, z2, o);
    const float invZ2 = 1.f / z2;

    __half* prow = Pout + gid * CS;
    #pragma unroll
    for (int g = 0; g < 8; g++) {
        if (g <= glim) {
            __half2 p0 = __floats2half2_rn(s[g*4+0] * invZ2, s[g*4+1] * invZ2);
            __half2 p1 = __floats2half2_rn(s[g*4+2] * invZ2, s[g*4+3] * invZ2);
            uint2 pk;
            pk.x = *(uint32_t*)&p0;
            pk.y = *(uint32_t*)&p1;
            *(uint2*)(prow + g * 128 + lane * 4) = pk;
        }
    }
}

// ============================================================================
// AV HMMA (triangular, heavy-blocks-first), single V plane
// ============================================================================
#define AROWB 144
#define AP_BYTES (128*AROWB)
#define AV_BYTES (64*AROWB)          // single V plane
#define AV_BUF (AP_BYTES + AV_BYTES) // 27648
#define AV_SMEM (2*AV_BUF)           // 55296

__global__ void __launch_bounds__(256, 2) av_mma_kernel(
    const __half* __restrict__ Pg, const __half* __restrict__ Vt,
    __half* __restrict__ Cc)
{
    extern __shared__ char smem[];
    const uint32_t sbase = smem_u32(smem);

    const int z  = blockIdx.z;
    const int yb = gridDim.y - 1 - blockIdx.y;
    const int m0 = yb * 128;
    const __half* Pz = Pg + (size_t)z * CS * CS;
    const __half* Vz = Vt + (size_t)z * CDK * CS;

    const int tid  = threadIdx.x;
    const int warp = tid >> 5;
    const int lane = tid & 31;
    const int wm   = warp & 3;
    const int wn   = warp >> 2;
    const int lane8 = lane & 7;
    const int lg    = lane >> 3;

    float acc[2][4][4];
    #pragma unroll
    for (int i = 0; i < 2; i++)
        #pragma unroll
        for (int j = 0; j < 4; j++)
            #pragma unroll
            for (int c = 0; c < 4; c++) acc[i][j][c] = 0.f;

    const int nch = 2 * (yb + 1);

    auto load_chunk = [&](int ic, int b) {
        const int k0 = ic * 64;
        #pragma unroll
        for (int i = 0; i < 6; i++) {
            int seg = i * 256 + tid;           // 0..1535
            uint32_t dstb = sbase + b * AV_BUF;
            if (seg < 1024) {                  // P tile: 128 rows x 8 segs
                int r = seg >> 3, c = seg & 7;
                const __half* src = Pz + (size_t)(m0 + r) * CS + k0 + c * 8;
                cp_async16(dstb + r * AROWB + c * 16, src);
            } else {                           // V tile: 64 rows x 8 segs
                int s2 = seg - 1024;
                int r = s2 >> 3, c = s2 & 7;
                const __half* src = Vz + (size_t)r * CS + k0 + c * 8;
                cp_async16(dstb + AP_BYTES + r * AROWB + c * 16, src);
            }
        }
        cp_commit();
    };

    load_chunk(0, 0);
    load_chunk(1, 1);

    for (int ic = 0; ic < nch; ic++) {
        const int b = ic & 1;
        if (ic == nch - 1) cp_wait<0>(); else cp_wait<1>();
        __syncthreads();

        const uint32_t bb = sbase + b * AV_BUF;
        #pragma unroll
        for (int kk = 0; kk < 4; kk++) {
            uint32_t af[2][4];
            #pragma unroll
            for (int tm = 0; tm < 2; tm++) {
                int row = wm * 32 + tm * 16 + lane8 + (lg & 1) * 8;
                int col = kk * 32 + (lg >> 1) * 16;
                ldm4(af[tm], bb + row * AROWB + col);
            }
            #pragma unroll
            for (int tp = 0; tp < 2; tp++) {
                uint32_t bhf[4];
                int row = wn * 32 + tp * 16 + lane8 + (lg >> 1) * 8;
                int col = kk * 32 + (lg & 1) * 16;
                ldm4(bhf, bb + AP_BYTES + row * AROWB + col);
                #pragma unroll
                for (int tm = 0; tm < 2; tm++) {
                    #pragma unroll
                    for (int h2 = 0; h2 < 2; h2++)
                        mma_f16(acc[tm][tp * 2 + h2], af[tm], bhf + h2 * 2);
                }
            }
        }
        __syncthreads();
        if (ic + 2 < nch) load_chunk(ic + 2, b);
    }

    const int gid = lane >> 2;
    const int tig = lane & 3;
    const int b_ = z >> 4;
    const int h  = z & 15;
    #pragma unroll
    for (int tm = 0; tm < 2; tm++) {
        #pragma unroll
        for (int tn = 0; tn < 4; tn++) {
            float* c = acc[tm][tn];
            const int m = m0 + wm * 32 + tm * 16 + gid;
            const int n = wn * 32 + tn * 8 + tig * 2;
            #pragma unroll
            for (int rr = 0; rr < 2; rr++) {
                const int s = m + rr * 8;
                const float va = c[rr * 2 + 0], vb = c[rr * 2 + 1];
                size_t idx = ((size_t)(b_ * CS + s)) * CDM + h * CDK + n;
                __half2 hp = __floats2half2_rn(va, vb);
                *(uint32_t*)(Cc + idx) = *(uint32_t*)&hp;
            }
        }
    }
}

// ============================================================================
// Launch sequence (R14 structure)
// ============================================================================
extern "C" void kernel_launch(void* const* d_in, const int* in_sizes, int n_in,
                              void* d_out, int out_size)
{
    const float* q      = (const float*)d_in[0];
    const float* k      = (const float*)d_in[1];
    const float* v      = (const float*)d_in[2];
    const float* Wq     = (const float*)d_in[3];
    const float* bq     = (const float*)d_in[4];
    const float* Wk     = (const float*)d_in[5];
    const float* bk     = (const float*)d_in[6];
    const float* Wv     = (const float*)d_in[7];
    const float* bv     = (const float*)d_in[8];
    const float* Wo     = (const float*)d_in[9];
    const float* bo     = (const float*)d_in[10];
    const float* gammas = (const float*)d_in[11];
    float* out = (float*)d_out;

    __half *sc, *ps, *vts, *qhs, *khs, *qs, *ks, *vs, *ccs, *wqs, *wks, *wvs, *wos;
    cudaGetSymbolAddress((void**)&sc,  g_scores);
    cudaGetSymbolAddress((void**)&ps,  g_ps);
    cudaGetSymbolAddress((void**)&vts, g_vts);
    cudaGetSymbolAddress((void**)&qhs, g_qhs);
    cudaGetSymbolAddress((void**)&khs, g_khs);
    cudaGetSymbolAddress((void**)&qs,  g_qs);
    cudaGetSymbolAddress((void**)&ks,  g_ks);
    cudaGetSymbolAddress((void**)&vs,  g_vs);
    cudaGetSymbolAddress((void**)&ccs, g_ccs);
    cudaGetSymbolAddress((void**)&wqs, g_wqs);
    cudaGetSymbolAddress((void**)&wks, g_wks);
    cudaGetSymbolAddress((void**)&wvs, g_wvs);
    cudaGetSymbolAddress((void**)&wos, g_wos);

    cudaFuncSetAttribute((const void*)mma_gemm_kernel<4>, cudaFuncAttributeMaxDynamicSharedMemorySize, MM_SMEM);
    cudaFuncSetAttribute((const void*)mma_gemm_kernel<3>, cudaFuncAttributeMaxDynamicSharedMemorySize, MM_SMEM);
    cudaFuncSetAttribute((const void*)mma_gemm_kernel<0>, cudaFuncAttributeMaxDynamicSharedMemorySize, MM_SMEM);
    cudaFuncSetAttribute(qk_gemm_kernel, cudaFuncAttributeMaxDynamicSharedMemorySize, QK_SMEM);
    cudaFuncSetAttribute(av_mma_kernel,  cudaFuncAttributeMaxDynamicSharedMemorySize, AV_SMEM);

    const int  M    = CB * CS;              // 4096
    const long nBig = (long)M * CDM;        // 4 M elems
    const long nW   = (long)CDM * CDM;      // 1 M elems

    // activations + all weights -> fp16 hi only (R14 proven: separate launches)
    cvt_f16_kernel<<<(unsigned)(nBig/1024), 256>>>(q,  qs,  nBig);
    cvt_f16_kernel<<<(unsigned)(nBig/1024), 256>>>(k,  ks,  nBig);
    cvt_f16_kernel<<<(unsigned)(nBig/1024), 256>>>(v,  vs,  nBig);
    cvt_f16_kernel<<<(unsigned)(nW/1024),   256>>>(Wq, wqs, nW);
    cvt_f16_kernel<<<(unsigned)(nW/1024),   256>>>(Wk, wks, nW);
    cvt_f16_kernel<<<(unsigned)(nW/1024),   256>>>(Wv, wvs, nW);
    cvt_f16_kernel<<<(unsigned)(nW/1024),   256>>>(Wo, wos, nW);

    // Q/K -> fp16 single plane (head-scattered)
    mma_gemm_kernel<4><<<dim3(CDM/128, M/128), 256, MM_SMEM>>>(
        qs, wqs, bq, nullptr, qhs, M, CDM, CDM, 1.f);
    mma_gemm_kernel<4><<<dim3(CDM/128, M/128), 256, MM_SMEM>>>(
        ks, wks, bk, nullptr, khs, M, CDM, CDM, 1.f);
    // V -> fp16 single plane, transposed per head
    mma_gemm_kernel<3><<<dim3(CDM/128, M/128), 256, MM_SMEM>>>(
        vs, wvs, bv, nullptr, vts, M, CDM, CDM, 1.f);

    // scores = Qh @ Kh^T / 8 (fp16 out), batched over bh
    qk_gemm_kernel<<<dim3(CS/128, CS/128, CBH), 256, QK_SMEM>>>(qhs, khs, sc);

    // row ops (warp per row) -> fp16 P (causal-limited writes)
    rowops_kernel<<<CBH * CS / 8, 256>>>(sc, gammas, ps);

    // AV (triangular, heavy-first, single V plane) -> concat fp16
    av_mma_kernel<<<dim3(1, CS/128, CBH), 256, AV_SMEM>>>(ps, vts, ccs);

    // output projection
    mma_gemm_kernel<0><<<dim3(CDM/128, M/128), 256, MM_SMEM>>>(
        ccs, wos, bo, out, nullptr, M, CDM, CDM, 1.f);
}